// round 8
// baseline (speedup 1.0000x reference)
#include <cuda_runtime.h>
#include <cuda_bf16.h>
#include <cuda_fp16.h>
#include <cstdint>

// Problem constants (fixed by the dataset)
#define NN   4096
#define FDIM 256
#define BB   8
#define MTOT (BB * NN)          // 32768 rows
#define WPR  (NN / 32)
#define MAXD 128

// -------- scratch (static __device__ arrays; no allocation allowed) --------
__device__ unsigned g_adj[NN * WPR];
__device__ int      g_deg[NN];
__device__ int      g_nbr[NN * MAXD];
__device__ __align__(16) __half        g_xth[(size_t)MTOT * FDIM];  // 16 MB fp16 xt
__device__ __align__(16) __nv_bfloat16 g_wh[FDIM * FDIM];           // W^T hi [n][k]
__device__ __align__(16) __nv_bfloat16 g_wl[FDIM * FDIM];           // W^T lo [n][k]

// ---------------------------------------------------------------------------
// Kernel 1: fused init — zero bitmask+degree AND weight transpose/split
// grid 512 x 256 = 131072 threads
// ---------------------------------------------------------------------------
__global__ void k_init(const float* __restrict__ w) {
    int i = blockIdx.x * blockDim.x + threadIdx.x;
    ((uint4*)g_adj)[i] = make_uint4(0u, 0u, 0u, 0u);     // 131072 uint4 = whole g_adj
    if (i < NN) g_deg[i] = 0;
    if (i < FDIM * FDIM) {
        int k = i >> 8, n = i & 255;
        float v = w[i];
        __nv_bfloat16 h = __float2bfloat16(v);
        __nv_bfloat16 l = __float2bfloat16(v - __bfloat162float(h));
        g_wh[n * FDIM + k] = h;
        g_wl[n * FDIM + k] = l;
    }
}

// ---------------------------------------------------------------------------
// Kernel 2: build dedup'd neighbor lists
// ---------------------------------------------------------------------------
__global__ void k_edges(const int* __restrict__ ei, int E) {
    int e = blockIdx.x * blockDim.x + threadIdx.x;
    if (e >= E) return;
    int src = ei[e];
    int dst = ei[E + e];
    unsigned mask = 1u << (dst & 31);
    unsigned old = atomicOr(&g_adj[src * WPR + (dst >> 5)], mask);
    if (!(old & mask)) {
        int pos = atomicAdd(&g_deg[src], 1);
        if (pos < MAXD) g_nbr[src * MAXD + pos] = dst;
    }
}

// ---------------------------------------------------------------------------
// Kernel 3: xt = x @ W via bf16 mma.sync, 3-term split.
// A loaded directly from global; B (hi+lo, full K) smem-resident.
// Register diet: no next-step prefetch buffer, ldsm.x4 fetches hi+lo planes
// in one instruction -> target 3 CTAs/SM.
// ---------------------------------------------------------------------------
#define BSTR  264                // B smem row stride in halves (256 + 8 pad)
#define SB_H  0                  // 64 * 264 * 2 = 33792 bytes per plane
#define SB_L  33792
#define S_TOT 67584

extern __shared__ char dsm[];

__device__ __forceinline__ uint32_t smem_u32(const void* p) {
    uint32_t a;
    asm("{ .reg .u64 t; cvta.to.shared.u64 t, %1; cvt.u32.u64 %0, t; }"
        : "=r"(a) : "l"(p));
    return a;
}
// x4: lane groups 0-7/8-15/16-23/24-31 supply addresses for 4 independent
// 8x8 tiles -> fetch {bH_klo, bH_khi, bL_klo, bL_khi} in ONE instruction.
__device__ __forceinline__ void ldsm_x4(uint32_t* r, uint32_t addr) {
    asm volatile("ldmatrix.sync.aligned.m8n8.x4.shared.b16 {%0,%1,%2,%3}, [%4];"
                 : "=r"(r[0]), "=r"(r[1]), "=r"(r[2]), "=r"(r[3]) : "r"(addr));
}
__device__ __forceinline__ void mma_bf16(float* c, const uint32_t* a,
                                         const uint32_t* b) {
    asm volatile(
        "mma.sync.aligned.m16n8k16.row.col.f32.bf16.bf16.f32 "
        "{%0,%1,%2,%3}, {%4,%5,%6,%7}, {%8,%9}, {%0,%1,%2,%3};"
        : "+f"(c[0]), "+f"(c[1]), "+f"(c[2]), "+f"(c[3])
        : "r"(a[0]), "r"(a[1]), "r"(a[2]), "r"(a[3]), "r"(b[0]), "r"(b[1]));
}
__device__ __forceinline__ uint32_t packbf2(float a, float b) {
    __nv_bfloat162 p = __floats2bfloat162_rn(a, b);
    return *(uint32_t*)&p;
}
__device__ __forceinline__ void cvt_hilo(float2 v, uint32_t& h, uint32_t& l) {
    __nv_bfloat16 h0 = __float2bfloat16(v.x);
    __nv_bfloat16 h1 = __float2bfloat16(v.y);
    h = (uint32_t)__bfloat16_as_ushort(h0) |
        ((uint32_t)__bfloat16_as_ushort(h1) << 16);
    l = packbf2(v.x - __bfloat162float(h0), v.y - __bfloat162float(h1));
}

__global__ void __launch_bounds__(256, 3)
k_gemm_tc(const float* __restrict__ x) {
    const int tid  = threadIdx.x;
    const int lane = tid & 31;
    const int w    = tid >> 5;
    const int wm   = w >> 1;          // 0..3 (32-row block)
    const int wn   = w & 1;           // 0..1 (32-col block)
    const int n0   = blockIdx.x * 64;
    const int m0   = blockIdx.y * 128;
    const uint32_t sb = smem_u32(dsm);

    // ---- preload B (hi + lo, 64 n x 256 k) into smem ----
    #pragma unroll
    for (int q = 0; q < 8; q++) {
        int idx = q * 256 + tid;
        int n = idx >> 5;
        int u = idx & 31;
        *(uint4*)(dsm + SB_H + n * (BSTR * 2) + u * 16) =
            *(const uint4*)&g_wh[(size_t)(n0 + n) * FDIM + u * 8];
        *(uint4*)(dsm + SB_L + n * (BSTR * 2) + u * 16) =
            *(const uint4*)&g_wl[(size_t)(n0 + n) * FDIM + u * 8];
    }
    __syncthreads();

    // A fragment base (mma m16n8k16 A layout == row-major float2 loads)
    const float* ap = x + (size_t)(m0 + wm * 32 + (lane >> 2)) * FDIM +
                      ((lane & 3) << 1);
    // B ldsm.x4 base: lane-group selects plane (H/L) and k half (0/8)
    const uint32_t plane = ((lane >> 4) & 1) ? SB_L : SB_H;
    const uint32_t bbase = sb + plane +
                           (uint32_t)(wn * 32 + (lane & 7)) * (BSTR * 2) +
                           (uint32_t)(((lane >> 3) & 1) * 8) * 2;

    float acc[2][4][4];
    #pragma unroll
    for (int i = 0; i < 2; i++)
        #pragma unroll
        for (int j = 0; j < 4; j++)
            #pragma unroll
            for (int r = 0; r < 4; r++) acc[i][j][r] = 0.f;

    #pragma unroll
    for (int kk = 0; kk < 16; kk++) {
        const int kb = kk * 16;

        // A loads for this k-step (latency hidden by cross-warp rotation)
        float2 pv[2][4];
        #pragma unroll
        for (int i = 0; i < 2; i++) {
            const float* p = ap + i * 16 * FDIM + kb;
            pv[i][0] = *(const float2*)(p);
            pv[i][1] = *(const float2*)(p + 8 * FDIM);
            pv[i][2] = *(const float2*)(p + 8);
            pv[i][3] = *(const float2*)(p + 8 * FDIM + 8);
        }

        // B fragments: one x4 per j gives {bH_lo, bH_hi, bL_lo, bL_hi}
        uint32_t bb[4][4];
        #pragma unroll
        for (int j = 0; j < 4; j++)
            ldsm_x4(bb[j], bbase + (uint32_t)kb * 2 + j * 8 * (BSTR * 2));

        // convert A to hi/lo fragments
        uint32_t aH[2][4], aL[2][4];
        #pragma unroll
        for (int i = 0; i < 2; i++)
            #pragma unroll
            for (int q = 0; q < 4; q++)
                cvt_hilo(pv[i][q], aH[i][q], aL[i][q]);

        // 24 mma: Ah*Bh + Ah*Bl + Al*Bh
        #pragma unroll
        for (int i = 0; i < 2; i++)
            #pragma unroll
            for (int j = 0; j < 4; j++) mma_bf16(acc[i][j], aH[i], &bb[j][0]);
        #pragma unroll
        for (int i = 0; i < 2; i++)
            #pragma unroll
            for (int j = 0; j < 4; j++) mma_bf16(acc[i][j], aH[i], &bb[j][2]);
        #pragma unroll
        for (int i = 0; i < 2; i++)
            #pragma unroll
            for (int j = 0; j < 4; j++) mma_bf16(acc[i][j], aL[i], &bb[j][0]);
    }

    // ---- epilogue: D fragment -> g_xth (fp16) ----
    #pragma unroll
    for (int i = 0; i < 2; i++) {
        #pragma unroll
        for (int j = 0; j < 4; j++) {
            int m = m0 + wm * 32 + i * 16 + (lane >> 2);
            int n = n0 + wn * 32 + j * 8 + (lane & 3) * 2;
            *(__half2*)&g_xth[(size_t)m * FDIM + n] =
                __float22half2_rn(make_float2(acc[i][j][0], acc[i][j][1]));
            *(__half2*)&g_xth[(size_t)(m + 8) * FDIM + n] =
                __float22half2_rn(make_float2(acc[i][j][2], acc[i][j][3]));
        }
    }
}

// ---------------------------------------------------------------------------
// Kernel 4: sparse aggregation over fp16 xt (unchanged from round 7).
// ---------------------------------------------------------------------------
__global__ void __launch_bounds__(256)
k_agg(const float* __restrict__ bias, float* __restrict__ out) {
    const int src  = blockIdx.x;
    const int tid  = threadIdx.x;
    const int half = tid >> 7;
    const int t    = tid & 127;
    const int f    = t << 1;

    __shared__ int    snb[MAXD];
    __shared__ float2 red[128][BB];

    int deg = g_deg[src];
    if (deg > MAXD) deg = MAXD;
    if (tid < deg) snb[tid] = g_nbr[src * MAXD + tid];
    __syncthreads();

    const int i0 = half ? (deg >> 1) : 0;
    const int i1 = half ? deg : (deg >> 1);

    float2 acc[BB];
    #pragma unroll
    for (int b = 0; b < BB; b++) acc[b] = make_float2(0.f, 0.f);

    const size_t batch_stride = (size_t)NN * FDIM;

    int i = i0;
    for (; i + 2 <= i1; i += 2) {
        const __half* p0 = &g_xth[(size_t)snb[i]     * FDIM + f];
        const __half* p1 = &g_xth[(size_t)snb[i + 1] * FDIM + f];
        __half2 v0[BB], v1[BB];
        #pragma unroll
        for (int b = 0; b < BB; b++) v0[b] = *(const __half2*)(p0 + b * batch_stride);
        #pragma unroll
        for (int b = 0; b < BB; b++) v1[b] = *(const __half2*)(p1 + b * batch_stride);
        #pragma unroll
        for (int b = 0; b < BB; b++) {
            float2 a = __half22float2(v0[b]);
            float2 c = __half22float2(v1[b]);
            acc[b].x += a.x + c.x;
            acc[b].y += a.y + c.y;
        }
    }
    if (i < i1) {
        const __half* p0 = &g_xth[(size_t)snb[i] * FDIM + f];
        #pragma unroll
        for (int b = 0; b < BB; b++) {
            float2 a = __half22float2(*(const __half2*)(p0 + b * batch_stride));
            acc[b].x += a.x;
            acc[b].y += a.y;
        }
    }

    if (half) {
        #pragma unroll
        for (int b = 0; b < BB; b++) red[t][b] = acc[b];
    }
    __syncthreads();

    if (!half) {
        const float inv = 1.0f / ((float)deg + 1e-6f);
        const float2 bf = *(const float2*)&bias[f];
        #pragma unroll
        for (int b = 0; b < BB; b++) {
            float2 o = red[t][b];
            o.x = (acc[b].x + o.x) * inv + bf.x;
            o.y = (acc[b].y + o.y) * inv + bf.y;
            *(float2*)&out[((size_t)b * NN + src) * FDIM + f] = o;
        }
    }
}

// ---------------------------------------------------------------------------
extern "C" void kernel_launch(void* const* d_in, const int* in_sizes, int n_in,
                              void* d_out, int out_size) {
    const float* x    = (const float*)d_in[0];   // (8, 4096, 256) f32
    const int*   ei   = (const int*)  d_in[1];   // (2, 131072) i32
    const float* w    = (const float*)d_in[2];   // (256, 256) f32
    const float* bias = (const float*)d_in[3];   // (256,) f32
    float* out = (float*)d_out;

    const int E = in_sizes[1] / 2;

    cudaFuncSetAttribute(k_gemm_tc, cudaFuncAttributeMaxDynamicSharedMemorySize,
                         S_TOT);

    k_init<<<512, 256>>>(w);
    k_edges<<<(E + 255) / 256, 256>>>(ei, E);
    k_gemm_tc<<<dim3(4, MTOT / 128), 256, S_TOT>>>(x);
    k_agg<<<NN, 256>>>(bias, out);
}

// round 9
// speedup vs baseline: 1.2579x; 1.2579x over previous
#include <cuda_runtime.h>
#include <cuda_fp16.h>
#include <cstdint>

// Problem constants (fixed by the dataset)
#define NN   4096
#define FDIM 256
#define BB   8
#define MTOT (BB * NN)          // 32768 rows
#define WPR  (NN / 32)
#define MAXD 128

// -------- scratch (static __device__ arrays; no allocation allowed) --------
__device__ unsigned g_adj[NN * WPR];
__device__ int      g_deg[NN];
__device__ int      g_nbr[NN * MAXD];
__device__ __align__(16) __half g_xth[(size_t)MTOT * FDIM];  // 16 MB fp16 xt
__device__ __align__(16) __half g_wt[FDIM * FDIM];           // W^T fp16 [n][k]

// ---------------------------------------------------------------------------
// Kernel 1: fused init — zero bitmask+degree AND weight transpose (fp16)
// ---------------------------------------------------------------------------
__global__ void k_init(const float* __restrict__ w) {
    int i = blockIdx.x * blockDim.x + threadIdx.x;
    ((uint4*)g_adj)[i] = make_uint4(0u, 0u, 0u, 0u);   // 131072 uint4 = whole g_adj
    if (i < NN) g_deg[i] = 0;
    if (i < FDIM * FDIM) {
        int k = i >> 8, n = i & 255;
        g_wt[n * FDIM + k] = __float2half_rn(w[i]);
    }
}

// ---------------------------------------------------------------------------
// Kernel 2: build dedup'd neighbor lists
// ---------------------------------------------------------------------------
__global__ void k_edges(const int* __restrict__ ei, int E) {
    int e = blockIdx.x * blockDim.x + threadIdx.x;
    if (e >= E) return;
    int src = ei[e];
    int dst = ei[E + e];
    unsigned mask = 1u << (dst & 31);
    unsigned old = atomicOr(&g_adj[src * WPR + (dst >> 5)], mask);
    if (!(old & mask)) {
        int pos = atomicAdd(&g_deg[src], 1);
        if (pos < MAXD) g_nbr[src * MAXD + pos] = dst;
    }
}

// ---------------------------------------------------------------------------
// Kernel 3: xt = x @ W via single-term fp16 mma.sync (fp32 accumulate).
// A loaded directly from global (fragment layout == row-major float2),
// converted to fp16 in registers. B (full K=256, fp16) resident in smem.
// ---------------------------------------------------------------------------
#define BSTR  264                // B smem row stride in halves (256 + 8 pad)
#define S_TOT (64 * BSTR * 2)    // 33792 bytes

extern __shared__ char dsm[];

__device__ __forceinline__ uint32_t smem_u32(const void* p) {
    uint32_t a;
    asm("{ .reg .u64 t; cvta.to.shared.u64 t, %1; cvt.u32.u64 %0, t; }"
        : "=r"(a) : "l"(p));
    return a;
}
// x4: lane groups give 4 tiles: {j_even klo, j_even khi, j_odd klo, j_odd khi}
__device__ __forceinline__ void ldsm_x4(uint32_t* r, uint32_t addr) {
    asm volatile("ldmatrix.sync.aligned.m8n8.x4.shared.b16 {%0,%1,%2,%3}, [%4];"
                 : "=r"(r[0]), "=r"(r[1]), "=r"(r[2]), "=r"(r[3]) : "r"(addr));
}
__device__ __forceinline__ void mma_f16(float* c, const uint32_t* a,
                                        const uint32_t* b) {
    asm volatile(
        "mma.sync.aligned.m16n8k16.row.col.f32.f16.f16.f32 "
        "{%0,%1,%2,%3}, {%4,%5,%6,%7}, {%8,%9}, {%0,%1,%2,%3};"
        : "+f"(c[0]), "+f"(c[1]), "+f"(c[2]), "+f"(c[3])
        : "r"(a[0]), "r"(a[1]), "r"(a[2]), "r"(a[3]), "r"(b[0]), "r"(b[1]));
}

__global__ void __launch_bounds__(256)
k_gemm_tc(const float* __restrict__ x) {
    const int tid  = threadIdx.x;
    const int lane = tid & 31;
    const int w    = tid >> 5;
    const int wm   = w >> 1;          // 0..3 (32-row block)
    const int wn   = w & 1;           // 0..1 (32-col block)
    const int n0   = blockIdx.x * 64;
    const int m0   = blockIdx.y * 128;
    const uint32_t sb = smem_u32(dsm);

    // ---- preload B (64 n x 256 k fp16) into smem ----
    #pragma unroll
    for (int q = 0; q < 8; q++) {
        int idx = q * 256 + tid;
        int n = idx >> 5;
        int u = idx & 31;
        *(uint4*)(dsm + n * (BSTR * 2) + u * 16) =
            *(const uint4*)&g_wt[(size_t)(n0 + n) * FDIM + u * 8];
    }
    __syncthreads();

    // A fragment base (mma m16n8k16 A layout == row-major float2 loads)
    const float* ap = x + (size_t)(m0 + wm * 32 + (lane >> 2)) * FDIM +
                      ((lane & 3) << 1);
    // B ldsm.x4 base: (lane>>4)&1 -> j within pair, (lane>>3)&1 -> k-half
    const uint32_t bbase = sb +
        (uint32_t)(wn * 32 + ((lane >> 4) & 1) * 8 + (lane & 7)) * (BSTR * 2) +
        (uint32_t)(((lane >> 3) & 1) * 8) * 2;

    float acc[2][4][4];
    #pragma unroll
    for (int i = 0; i < 2; i++)
        #pragma unroll
        for (int j = 0; j < 4; j++)
            #pragma unroll
            for (int r = 0; r < 4; r++) acc[i][j][r] = 0.f;

    // prologue: A loads for k-step 0
    float2 pv[2][4];
    #pragma unroll
    for (int i = 0; i < 2; i++) {
        const float* p = ap + i * 16 * FDIM;
        pv[i][0] = *(const float2*)(p);
        pv[i][1] = *(const float2*)(p + 8 * FDIM);
        pv[i][2] = *(const float2*)(p + 8);
        pv[i][3] = *(const float2*)(p + 8 * FDIM + 8);
    }

    #pragma unroll
    for (int kk = 0; kk < 16; kk++) {
        // prefetch next A chunk (known win from rounds 6/7 vs round 8)
        float2 nv[2][4];
        if (kk + 1 < 16) {
            const int kn = (kk + 1) * 16;
            #pragma unroll
            for (int i = 0; i < 2; i++) {
                const float* p = ap + i * 16 * FDIM + kn;
                nv[i][0] = *(const float2*)(p);
                nv[i][1] = *(const float2*)(p + 8 * FDIM);
                nv[i][2] = *(const float2*)(p + 8);
                nv[i][3] = *(const float2*)(p + 8 * FDIM + 8);
            }
        }

        // convert A fragments to fp16 (one cvt per float2)
        uint32_t aF[2][4];
        #pragma unroll
        for (int i = 0; i < 2; i++)
            #pragma unroll
            for (int q = 0; q < 4; q++) {
                __half2 h = __float22half2_rn(pv[i][q]);
                aF[i][q] = *(uint32_t*)&h;
            }

        // B fragments: one ldsm.x4 per j-pair; 8 mma total
        const uint32_t kb = (uint32_t)(kk * 16) * 2;
        #pragma unroll
        for (int j2 = 0; j2 < 2; j2++) {
            uint32_t bb[4];
            ldsm_x4(bb, bbase + kb + (uint32_t)(j2 * 16) * (BSTR * 2));
            #pragma unroll
            for (int i = 0; i < 2; i++) {
                mma_f16(acc[i][2 * j2 + 0], aF[i], &bb[0]);
                mma_f16(acc[i][2 * j2 + 1], aF[i], &bb[2]);
            }
        }

        #pragma unroll
        for (int i = 0; i < 2; i++)
            #pragma unroll
            for (int q = 0; q < 4; q++) pv[i][q] = nv[i][q];
    }

    // ---- epilogue: D fragment -> g_xth (fp16) ----
    #pragma unroll
    for (int i = 0; i < 2; i++) {
        #pragma unroll
        for (int j = 0; j < 4; j++) {
            int m = m0 + wm * 32 + i * 16 + (lane >> 2);
            int n = n0 + wn * 32 + j * 8 + (lane & 3) * 2;
            *(__half2*)&g_xth[(size_t)m * FDIM + n] =
                __float22half2_rn(make_float2(acc[i][j][0], acc[i][j][1]));
            *(__half2*)&g_xth[(size_t)(m + 8) * FDIM + n] =
                __float22half2_rn(make_float2(acc[i][j][2], acc[i][j][3]));
        }
    }
}

// ---------------------------------------------------------------------------
// Kernel 4: sparse aggregation. Warp = batch (8 warps = 8 batches); each
// lane owns 8 features via one LDG.128 per neighbor. Neighbor pairs are
// pre-summed with HADD2 (fp16) then accumulated in fp32.
// ---------------------------------------------------------------------------
__global__ void __launch_bounds__(256)
k_agg(const float* __restrict__ bias, float* __restrict__ out) {
    const int src  = blockIdx.x;
    const int tid  = threadIdx.x;
    const int b    = tid >> 5;           // batch = warp
    const int lane = tid & 31;
    const int f    = lane << 3;          // 8 features per lane

    __shared__ int snb[MAXD];
    int deg = g_deg[src];
    if (deg > MAXD) deg = MAXD;
    if (tid < deg) snb[tid] = g_nbr[src * MAXD + tid];
    __syncthreads();

    const __half* __restrict__ base = g_xth + (size_t)b * NN * FDIM + f;

    float acc[8];
    #pragma unroll
    for (int q = 0; q < 8; q++) acc[q] = 0.f;

    int i = 0;
    for (; i + 2 <= deg; i += 2) {
        uint4 u0 = *(const uint4*)(base + (size_t)snb[i]     * FDIM);
        uint4 u1 = *(const uint4*)(base + (size_t)snb[i + 1] * FDIM);
        const uint32_t* w0 = (const uint32_t*)&u0;
        const uint32_t* w1 = (const uint32_t*)&u1;
        #pragma unroll
        for (int q = 0; q < 4; q++) {
            __half2 s = __hadd2(*(const __half2*)&w0[q],
                                *(const __half2*)&w1[q]);
            float2 fv = __half22float2(s);
            acc[2 * q]     += fv.x;
            acc[2 * q + 1] += fv.y;
        }
    }
    if (i < deg) {
        uint4 u0 = *(const uint4*)(base + (size_t)snb[i] * FDIM);
        const uint32_t* w0 = (const uint32_t*)&u0;
        #pragma unroll
        for (int q = 0; q < 4; q++) {
            float2 fv = __half22float2(*(const __half2*)&w0[q]);
            acc[2 * q]     += fv.x;
            acc[2 * q + 1] += fv.y;
        }
    }

    const float inv = 1.0f / ((float)deg + 1e-6f);
    const float4 bf0 = *(const float4*)&bias[f];
    const float4 bf1 = *(const float4*)&bias[f + 4];

    float* dst = &out[((size_t)b * NN + src) * FDIM + f];
    *(float4*)(dst)     = make_float4(acc[0] * inv + bf0.x, acc[1] * inv + bf0.y,
                                      acc[2] * inv + bf0.z, acc[3] * inv + bf0.w);
    *(float4*)(dst + 4) = make_float4(acc[4] * inv + bf1.x, acc[5] * inv + bf1.y,
                                      acc[6] * inv + bf1.z, acc[7] * inv + bf1.w);
}

// ---------------------------------------------------------------------------
extern "C" void kernel_launch(void* const* d_in, const int* in_sizes, int n_in,
                              void* d_out, int out_size) {
    const float* x    = (const float*)d_in[0];   // (8, 4096, 256) f32
    const int*   ei   = (const int*)  d_in[1];   // (2, 131072) i32
    const float* w    = (const float*)d_in[2];   // (256, 256) f32
    const float* bias = (const float*)d_in[3];   // (256,) f32
    float* out = (float*)d_out;

    const int E = in_sizes[1] / 2;

    cudaFuncSetAttribute(k_gemm_tc, cudaFuncAttributeMaxDynamicSharedMemorySize,
                         S_TOT);

    k_init<<<512, 256>>>(w);
    k_edges<<<(E + 255) / 256, 256>>>(ei, E);
    k_gemm_tc<<<dim3(4, MTOT / 128), 256, S_TOT>>>(x);
    k_agg<<<NN, 256>>>(bias, out);
}

// round 10
// speedup vs baseline: 1.5611x; 1.2411x over previous
#include <cuda_runtime.h>
#include <cuda_fp16.h>
#include <cstdint>

// Problem constants (fixed by the dataset)
#define NN   4096
#define FDIM 256
#define BB   8
#define MTOT (BB * NN)          // 32768 rows
#define WPR  (NN / 32)
#define MAXD 128

// -------- scratch (static __device__ arrays; no allocation allowed) --------
__device__ unsigned g_adj[NN * WPR];
__device__ int      g_deg[NN];
__device__ int      g_nbr[NN * MAXD];
__device__ __align__(16) __half g_xth[(size_t)MTOT * FDIM];  // 16 MB fp16 xt
__device__ __align__(16) __half g_wt[FDIM * FDIM];           // W^T fp16 [n][k]

// ---------------------------------------------------------------------------
// Kernel 1: fused init — zero bitmask+degree AND weight transpose (fp16)
// ---------------------------------------------------------------------------
__global__ void k_init(const float* __restrict__ w) {
    int i = blockIdx.x * blockDim.x + threadIdx.x;
    ((uint4*)g_adj)[i] = make_uint4(0u, 0u, 0u, 0u);   // 131072 uint4 = whole g_adj
    if (i < NN) g_deg[i] = 0;
    if (i < FDIM * FDIM) {
        int k = i >> 8, n = i & 255;
        g_wt[n * FDIM + k] = __float2half_rn(w[i]);
    }
}

// ---------------------------------------------------------------------------
// Kernel 2: build dedup'd neighbor lists
// ---------------------------------------------------------------------------
__global__ void k_edges(const int* __restrict__ ei, int E) {
    int e = blockIdx.x * blockDim.x + threadIdx.x;
    if (e >= E) return;
    int src = ei[e];
    int dst = ei[E + e];
    unsigned mask = 1u << (dst & 31);
    unsigned old = atomicOr(&g_adj[src * WPR + (dst >> 5)], mask);
    if (!(old & mask)) {
        int pos = atomicAdd(&g_deg[src], 1);
        if (pos < MAXD) g_nbr[src * MAXD + pos] = dst;
    }
}

// ---------------------------------------------------------------------------
// Kernel 3: xt = x @ W via single-term fp16 mma.sync (fp32 accumulate).
// CTA tile M=128 x N=128: A fragments loaded once from global are reused
// across BOTH 64-wide n-halves (halves A L2 traffic + cvt work vs N=64).
// B (128 n x 256 k fp16) resident in smem.
// ---------------------------------------------------------------------------
#define BSTR  264                 // B smem row stride in halves (256 + 8 pad)
#define S_TOT (128 * BSTR * 2)    // 67584 bytes

extern __shared__ char dsm[];

__device__ __forceinline__ uint32_t smem_u32(const void* p) {
    uint32_t a;
    asm("{ .reg .u64 t; cvta.to.shared.u64 t, %1; cvt.u32.u64 %0, t; }"
        : "=r"(a) : "l"(p));
    return a;
}
// x4: lane groups give 4 tiles: {j_even klo, j_even khi, j_odd klo, j_odd khi}
__device__ __forceinline__ void ldsm_x4(uint32_t* r, uint32_t addr) {
    asm volatile("ldmatrix.sync.aligned.m8n8.x4.shared.b16 {%0,%1,%2,%3}, [%4];"
                 : "=r"(r[0]), "=r"(r[1]), "=r"(r[2]), "=r"(r[3]) : "r"(addr));
}
__device__ __forceinline__ void mma_f16(float* c, const uint32_t* a,
                                        const uint32_t* b) {
    asm volatile(
        "mma.sync.aligned.m16n8k16.row.col.f32.f16.f16.f32 "
        "{%0,%1,%2,%3}, {%4,%5,%6,%7}, {%8,%9}, {%0,%1,%2,%3};"
        : "+f"(c[0]), "+f"(c[1]), "+f"(c[2]), "+f"(c[3])
        : "r"(a[0]), "r"(a[1]), "r"(a[2]), "r"(a[3]), "r"(b[0]), "r"(b[1]));
}

__global__ void __launch_bounds__(256)
k_gemm_tc(const float* __restrict__ x) {
    const int tid  = threadIdx.x;
    const int lane = tid & 31;
    const int w    = tid >> 5;
    const int wm   = w >> 1;          // 0..3 (32-row block)
    const int wn   = w & 1;           // 0..1 (64-col block)
    const int n0   = blockIdx.x * 128;
    const int m0   = blockIdx.y * 128;
    const uint32_t sb = smem_u32(dsm);

    // ---- preload B (128 n x 256 k fp16) into smem ----
    #pragma unroll
    for (int q = 0; q < 16; q++) {
        int idx = q * 256 + tid;          // 0..4095
        int n = idx >> 5;                 // 0..127
        int u = idx & 31;
        *(uint4*)(dsm + n * (BSTR * 2) + u * 16) =
            *(const uint4*)&g_wt[(size_t)(n0 + n) * FDIM + u * 8];
    }
    __syncthreads();

    // A fragment base (mma m16n8k16 A layout == row-major float2 loads)
    const float* ap = x + (size_t)(m0 + wm * 32 + (lane >> 2)) * FDIM +
                      ((lane & 3) << 1);
    // B ldsm.x4 base: (lane>>4)&1 -> j within pair, (lane>>3)&1 -> k-half
    const uint32_t bbase = sb +
        (uint32_t)(wn * 64 + ((lane >> 4) & 1) * 8 + (lane & 7)) * (BSTR * 2) +
        (uint32_t)(((lane >> 3) & 1) * 8) * 2;

    float acc[2][8][4];
    #pragma unroll
    for (int i = 0; i < 2; i++)
        #pragma unroll
        for (int j = 0; j < 8; j++)
            #pragma unroll
            for (int r = 0; r < 4; r++) acc[i][j][r] = 0.f;

    // prologue: A loads for k-step 0
    float2 pv[2][4];
    #pragma unroll
    for (int i = 0; i < 2; i++) {
        const float* p = ap + i * 16 * FDIM;
        pv[i][0] = *(const float2*)(p);
        pv[i][1] = *(const float2*)(p + 8 * FDIM);
        pv[i][2] = *(const float2*)(p + 8);
        pv[i][3] = *(const float2*)(p + 8 * FDIM + 8);
    }

    #pragma unroll
    for (int kk = 0; kk < 16; kk++) {
        // prefetch next A chunk
        float2 nv[2][4];
        if (kk + 1 < 16) {
            const int kn = (kk + 1) * 16;
            #pragma unroll
            for (int i = 0; i < 2; i++) {
                const float* p = ap + i * 16 * FDIM + kn;
                nv[i][0] = *(const float2*)(p);
                nv[i][1] = *(const float2*)(p + 8 * FDIM);
                nv[i][2] = *(const float2*)(p + 8);
                nv[i][3] = *(const float2*)(p + 8 * FDIM + 8);
            }
        }

        // convert A fragments to fp16
        uint32_t aF[2][4];
        #pragma unroll
        for (int i = 0; i < 2; i++)
            #pragma unroll
            for (int q = 0; q < 4; q++) {
                __half2 h = __float22half2_rn(pv[i][q]);
                aF[i][q] = *(uint32_t*)&h;
            }

        // B fragments: one ldsm.x4 per j-pair; 16 mma total (4 j-pairs)
        const uint32_t kb = (uint32_t)(kk * 16) * 2;
        #pragma unroll
        for (int j2 = 0; j2 < 4; j2++) {
            uint32_t bb[4];
            ldsm_x4(bb, bbase + kb + (uint32_t)(j2 * 16) * (BSTR * 2));
            #pragma unroll
            for (int i = 0; i < 2; i++) {
                mma_f16(acc[i][2 * j2 + 0], aF[i], &bb[0]);
                mma_f16(acc[i][2 * j2 + 1], aF[i], &bb[2]);
            }
        }

        #pragma unroll
        for (int i = 0; i < 2; i++)
            #pragma unroll
            for (int q = 0; q < 4; q++) pv[i][q] = nv[i][q];
    }

    // ---- epilogue: D fragment -> g_xth (fp16) ----
    #pragma unroll
    for (int i = 0; i < 2; i++) {
        #pragma unroll
        for (int j = 0; j < 8; j++) {
            int m = m0 + wm * 32 + i * 16 + (lane >> 2);
            int n = n0 + wn * 64 + j * 8 + (lane & 3) * 2;
            *(__half2*)&g_xth[(size_t)m * FDIM + n] =
                __float22half2_rn(make_float2(acc[i][j][0], acc[i][j][1]));
            *(__half2*)&g_xth[(size_t)(m + 8) * FDIM + n] =
                __float22half2_rn(make_float2(acc[i][j][2], acc[i][j][3]));
        }
    }
}

// ---------------------------------------------------------------------------
// Kernel 4: sparse aggregation. Warp = batch; lane owns 8 features via one
// LDG.128 per neighbor. 4-way neighbor unroll (MLP 4) with HADD2 pre-sums.
// ---------------------------------------------------------------------------
__global__ void __launch_bounds__(256)
k_agg(const float* __restrict__ bias, float* __restrict__ out) {
    const int src  = blockIdx.x;
    const int tid  = threadIdx.x;
    const int b    = tid >> 5;           // batch = warp
    const int lane = tid & 31;
    const int f    = lane << 3;          // 8 features per lane

    __shared__ int snb[MAXD];
    int deg = g_deg[src];
    if (deg > MAXD) deg = MAXD;
    if (tid < deg) snb[tid] = g_nbr[src * MAXD + tid];
    __syncthreads();

    const __half* __restrict__ base = g_xth + (size_t)b * NN * FDIM + f;

    float acc[8];
    #pragma unroll
    for (int q = 0; q < 8; q++) acc[q] = 0.f;

    int i = 0;
    for (; i + 4 <= deg; i += 4) {
        uint4 u0 = *(const uint4*)(base + (size_t)snb[i]     * FDIM);
        uint4 u1 = *(const uint4*)(base + (size_t)snb[i + 1] * FDIM);
        uint4 u2 = *(const uint4*)(base + (size_t)snb[i + 2] * FDIM);
        uint4 u3 = *(const uint4*)(base + (size_t)snb[i + 3] * FDIM);
        const uint32_t* w0 = (const uint32_t*)&u0;
        const uint32_t* w1 = (const uint32_t*)&u1;
        const uint32_t* w2 = (const uint32_t*)&u2;
        const uint32_t* w3 = (const uint32_t*)&u3;
        #pragma unroll
        for (int q = 0; q < 4; q++) {
            __half2 s01 = __hadd2(*(const __half2*)&w0[q],
                                  *(const __half2*)&w1[q]);
            __half2 s23 = __hadd2(*(const __half2*)&w2[q],
                                  *(const __half2*)&w3[q]);
            float2 f01 = __half22float2(s01);
            float2 f23 = __half22float2(s23);
            acc[2 * q]     += f01.x + f23.x;
            acc[2 * q + 1] += f01.y + f23.y;
        }
    }
    for (; i < deg; i++) {
        uint4 u0 = *(const uint4*)(base + (size_t)snb[i] * FDIM);
        const uint32_t* w0 = (const uint32_t*)&u0;
        #pragma unroll
        for (int q = 0; q < 4; q++) {
            float2 fv = __half22float2(*(const __half2*)&w0[q]);
            acc[2 * q]     += fv.x;
            acc[2 * q + 1] += fv.y;
        }
    }

    const float inv = 1.0f / ((float)deg + 1e-6f);
    const float4 bf0 = *(const float4*)&bias[f];
    const float4 bf1 = *(const float4*)&bias[f + 4];

    float* dst = &out[((size_t)b * NN + src) * FDIM + f];
    *(float4*)(dst)     = make_float4(acc[0] * inv + bf0.x, acc[1] * inv + bf0.y,
                                      acc[2] * inv + bf0.z, acc[3] * inv + bf0.w);
    *(float4*)(dst + 4) = make_float4(acc[4] * inv + bf1.x, acc[5] * inv + bf1.y,
                                      acc[6] * inv + bf1.z, acc[7] * inv + bf1.w);
}

// ---------------------------------------------------------------------------
extern "C" void kernel_launch(void* const* d_in, const int* in_sizes, int n_in,
                              void* d_out, int out_size) {
    const float* x    = (const float*)d_in[0];   // (8, 4096, 256) f32
    const int*   ei   = (const int*)  d_in[1];   // (2, 131072) i32
    const float* w    = (const float*)d_in[2];   // (256, 256) f32
    const float* bias = (const float*)d_in[3];   // (256,) f32
    float* out = (float*)d_out;

    const int E = in_sizes[1] / 2;

    cudaFuncSetAttribute(k_gemm_tc, cudaFuncAttributeMaxDynamicSharedMemorySize,
                         S_TOT);

    k_init<<<512, 256>>>(w);
    k_edges<<<(E + 255) / 256, 256>>>(ei, E);
    k_gemm_tc<<<dim3(2, MTOT / 128), 256, S_TOT>>>(x);
    k_agg<<<NN, 256>>>(bias, out);
}